// round 15
// baseline (speedup 1.0000x reference)
#include <cuda_runtime.h>
#include <cuda_fp16.h>
#include <cstdint>

// ---------------- problem constants ----------------
#define NROWS 8192
#define DIN   12544
#define HID   1024

// ---------------- GEMM tile config: 128x128 tile, 4 warps (64x64 warp tile) ----------------
#define BM 128
#define BN 128
#define BK 64
#define ROWB 144                           // 128B data + 16B pad (conflict-free ldmatrix)
#define STAGE_BYTES ((BM + BN) * ROWB)     // 36864
#define SMEM_BYTES (3 * STAGE_BYTES)       // 110592 -> 2 CTAs/SM

// fused-epilogue smem layout (reuses pipeline smem after mainloop)
#define TILE_PITCH 264
#define WSM_OFF    34048

// phase structure within the single fused launch
#define NCONV      72
#define PRECONV_MT 28
#define WAVE1_G    (PRECONV_MT * 8)        // 224 gemm1 tiles safe in wave 1
#define G1_BASE    NCONV                   // gemm1 tiles: bids [72, 584)
#define G2_BASE    (NCONV + 512)           // gemm2 tiles: bids [584, 1096)
#define GRID_TOTAL (NCONV + 512 + 512)

// prep kernel sections
#define CONV_BLOCKS 21952                  // 3584*12544/8/256
#define W1T_BX 32
#define W1T_BLOCKS (W1T_BX * (DIN / 32))   // 12544
#define W2T_BX 32
#define W2T_BLOCKS (W2T_BX * (HID / 32))   // 1024
#define ZERO_BLOCKS 128                    // g_HS: 8192*16 f32
#define PREP_BLOCKS (CONV_BLOCKS + W1T_BLOCKS + W2T_BLOCKS + ZERO_BLOCKS + 1)

// ---------------- device scratch ----------------
__device__ __align__(256) __half g_Xh [(size_t)NROWS * DIN];
__device__ __align__(256) __half g_W1T[(size_t)HID * DIN];
__device__ __align__(256) __half g_W2T[(size_t)HID * HID];
__device__ __align__(256) __half g_H1 [(size_t)NROWS * HID];
__device__ __align__(256) float  g_HS [(size_t)NROWS * 16];   // head partial sums
__device__ __align__(256) int    g_fc[64];                    // converter flags (->2)
__device__ __align__(256) int    g_f1[64];                    // gemm1 n-tile counts (->8)
__device__ __align__(256) int    g_f2[64];                    // gemm2 n-tile tickets (->8)

// ---------------- PTX helpers ----------------
__device__ __forceinline__ uint32_t smem_u32(const void* p) {
    uint32_t a;
    asm("{ .reg .u64 t; cvta.to.shared.u64 t, %1; cvt.u32.u64 %0, t; }" : "=r"(a) : "l"(p));
    return a;
}

#define CP_ASYNC16(dst, src) \
    asm volatile("cp.async.cg.shared.global [%0], [%1], 16;" :: "r"(dst), "l"(src) : "memory")
#define CP_ASYNC_COMMIT() asm volatile("cp.async.commit_group;" ::: "memory")
#define CP_ASYNC_WAIT1()  asm volatile("cp.async.wait_group 1;" ::: "memory")

__device__ __forceinline__ void ldm_x4(uint32_t& r0, uint32_t& r1, uint32_t& r2, uint32_t& r3,
                                       uint32_t addr) {
    asm volatile("ldmatrix.sync.aligned.m8n8.x4.shared.b16 {%0,%1,%2,%3}, [%4];"
                 : "=r"(r0), "=r"(r1), "=r"(r2), "=r"(r3) : "r"(addr));
}

__device__ __forceinline__ void mma16816(float* d, const uint32_t* a, const uint32_t* b) {
    asm volatile(
        "mma.sync.aligned.m16n8k16.row.col.f32.f16.f16.f32 "
        "{%0,%1,%2,%3}, {%4,%5,%6,%7}, {%8,%9}, {%0,%1,%2,%3};"
        : "+f"(d[0]), "+f"(d[1]), "+f"(d[2]), "+f"(d[3])
        : "r"(a[0]), "r"(a[1]), "r"(a[2]), "r"(a[3]), "r"(b[0]), "r"(b[1]));
}

// ---------------- prep: partial X convert + W1/W2 transpose + zero HS/flags ----------------
__global__ void __launch_bounds__(256) prep_kernel(const float* __restrict__ X, __half* __restrict__ Xh,
                                                   const float* __restrict__ W1, __half* __restrict__ W1T,
                                                   const float* __restrict__ W2, __half* __restrict__ W2T,
                                                   float* __restrict__ HS,
                                                   int* __restrict__ fc, int* __restrict__ f1,
                                                   int* __restrict__ f2) {
    __shared__ float tile[32][33];
    const int b   = blockIdx.x;
    const int tid = threadIdx.x;

    if (b < CONV_BLOCKS) {
        // X rows [0, 3584) -> fp16
        size_t i = (size_t)b * 256 + tid;
        const float4* p = reinterpret_cast<const float4*>(X) + i * 2;
        float4 a = p[0], c = p[1];
        __half2 h0 = __floats2half2_rn(a.x, a.y), h1 = __floats2half2_rn(a.z, a.w);
        __half2 h2 = __floats2half2_rn(c.x, c.y), h3 = __floats2half2_rn(c.z, c.w);
        uint4 v;
        v.x = *reinterpret_cast<uint32_t*>(&h0);
        v.y = *reinterpret_cast<uint32_t*>(&h1);
        v.z = *reinterpret_cast<uint32_t*>(&h2);
        v.w = *reinterpret_cast<uint32_t*>(&h3);
        reinterpret_cast<uint4*>(Xh)[i] = v;
        return;
    }
    if (b >= CONV_BLOCKS + W1T_BLOCKS + W2T_BLOCKS) {
        const int zb = b - (CONV_BLOCKS + W1T_BLOCKS + W2T_BLOCKS);
        if (zb < ZERO_BLOCKS) {
            size_t i = (size_t)zb * 256 + tid;
            reinterpret_cast<uint4*>(HS)[i] = make_uint4(0, 0, 0, 0);
        } else if (tid < 64) {
            fc[tid] = 0; f1[tid] = 0; f2[tid] = 0;
        }
        return;
    }

    const float* in; __half* out; int R, C, idx, bx;
    if (b < CONV_BLOCKS + W1T_BLOCKS) {
        idx = b - CONV_BLOCKS; in = W1; out = W1T; R = DIN; C = HID; bx = W1T_BX;
    } else {
        idx = b - CONV_BLOCKS - W1T_BLOCKS; in = W2; out = W2T; R = HID; C = HID; bx = W2T_BX;
    }
    const int c0 = (idx % bx) * 32, r0 = (idx / bx) * 32;
    const int x = tid & 31, y = tid >> 5;
    #pragma unroll
    for (int j = 0; j < 32; j += 8)
        tile[y + j][x] = in[(size_t)(r0 + y + j) * C + (c0 + x)];
    __syncthreads();
    #pragma unroll
    for (int j = 0; j < 32; j += 8)
        out[(size_t)(c0 + y + j) * R + (r0 + x)] = __float2half_rn(tile[x][y + j]);
}

// ---------------- fused mega-kernel: converters + GEMM1 + GEMM2(+heads) + finalize ----------------
__global__ void __launch_bounds__(128, 2)
fused_kernel(const __half* __restrict__ Xh, const __half* __restrict__ W1T,
             const __half* __restrict__ W2T,
             const float* __restrict__ b1, const float* __restrict__ b2,
             __half* __restrict__ H1, float* __restrict__ HS,
             const float* __restrict__ WcH, const float* __restrict__ WrH,
             const float* __restrict__ bc, const float* __restrict__ br,
             const float* __restrict__ Xf, __half* __restrict__ XhW,
             int* __restrict__ fc, int* __restrict__ f1, int* __restrict__ f2,
             float* __restrict__ out) {
    extern __shared__ char smem[];
    __shared__ int sTicket;
    const uint32_t sb = smem_u32(smem);
    const int tid  = threadIdx.x;
    const int wid  = tid >> 5, lane = tid & 31;
    const int wm   = wid & 1;
    const int wn   = wid >> 1;
    const int bid  = blockIdx.x;

    // ================= converter CTAs =================
    if (bid < NCONV) {
        const int cid = bid;
        const int mt  = PRECONV_MT + (cid >> 1);
        const size_t elem0 = ((size_t)mt * 128 + (size_t)(cid & 1) * 64) * DIN;
        const float4* src = reinterpret_cast<const float4*>(Xf + elem0);
        uint2* dst = reinterpret_cast<uint2*>(XhW + elem0);
        const int total = 64 * DIN / 4;
        for (int j = tid; j < total; j += 128) {
            float4 v = __ldg(src + j);
            __half2 h0 = __floats2half2_rn(v.x, v.y), h1 = __floats2half2_rn(v.z, v.w);
            uint2 o;
            o.x = *reinterpret_cast<uint32_t*>(&h0);
            o.y = *reinterpret_cast<uint32_t*>(&h1);
            dst[j] = o;
        }
        __threadfence();
        __syncthreads();
        if (tid == 0) atomicAdd(&fc[mt], 1);
        return;
    }

    // ================= tile setup =================
    const bool phase2 = (bid >= G2_BASE);
    int mt, m0, n0, K, nk;
    const __half *A, *B;
    const float *bias;
    if (!phase2) {
        const int g = bid - G1_BASE;
        mt = g >> 3; m0 = mt * BM; n0 = (g & 7) * BN;
        A = Xh; B = W1T; bias = b1; K = DIN; nk = DIN / BK;
        if (g >= WAVE1_G) {
            if (tid == 0)
                while (atomicAdd(&fc[mt], 0) < 2) __nanosleep(200);
            __syncthreads();
        }
    } else {
        const int g2 = bid - G2_BASE;
        mt = g2 >> 3; m0 = mt * BM; n0 = (g2 & 7) * BN;
        A = H1; B = W2T; bias = b2; K = HID; nk = HID / BK;
        if (tid == 0)
            while (atomicAdd(&f1[mt], 0) < 8) __nanosleep(200);
        __syncthreads();
    }

    const int cr = tid >> 3;
    const int cc = (tid & 7) * 16;

    const char* gA = reinterpret_cast<const char*>(A) + ((size_t)(m0 + cr) * K) * 2 + cc;
    const char* gB = reinterpret_cast<const char*>(B) + ((size_t)(n0 + cr) * K) * 2 + cc;
    const size_t rstride = (size_t)16 * K * 2;

    auto issue_stage = [&](int kc, int s) {
        const uint32_t abase = sb + s * STAGE_BYTES;
        const uint32_t bbase = abase + BM * ROWB;
        const size_t koff = (size_t)kc * (BK * 2);
        #pragma unroll
        for (int h = 0; h < 8; h++)
            CP_ASYNC16(abase + (cr + h * 16) * ROWB + cc, gA + koff + h * rstride);
        #pragma unroll
        for (int h = 0; h < 8; h++)
            CP_ASYNC16(bbase + (cr + h * 16) * ROWB + cc, gB + koff + h * rstride);
    };

    const int a_row = lane & 15, a_k8 = lane >> 4;
    const int b_row = (lane & 7) + ((lane >> 4) << 3), b_k8 = (lane >> 3) & 1;

    float acc[4][8][4];
    #pragma unroll
    for (int i = 0; i < 4; i++)
        #pragma unroll
        for (int j = 0; j < 8; j++)
            #pragma unroll
            for (int r = 0; r < 4; r++) acc[i][j][r] = 0.f;

    issue_stage(0, 0); CP_ASYNC_COMMIT();
    issue_stage(1, 1); CP_ASYNC_COMMIT();

    int s = 0, s2 = 2;
    for (int kc = 0; kc < nk; kc++) {
        CP_ASYNC_WAIT1();
        __syncthreads();

        if (kc + 2 < nk) issue_stage(kc + 2, s2);
        CP_ASYNC_COMMIT();

        const uint32_t abase = sb + s * STAGE_BYTES;
        const uint32_t bbase = abase + BM * ROWB;

        #pragma unroll
        for (int kk = 0; kk < 4; kk++) {
            uint32_t af[4][4], bf[8][2];
            #pragma unroll
            for (int mi = 0; mi < 4; mi++) {
                uint32_t addr = abase + (wm * 64 + mi * 16 + a_row) * ROWB + (kk * 2 + a_k8) * 16;
                ldm_x4(af[mi][0], af[mi][1], af[mi][2], af[mi][3], addr);
            }
            #pragma unroll
            for (int nb = 0; nb < 4; nb++) {
                uint32_t addr = bbase + (wn * 64 + nb * 16 + b_row) * ROWB + (kk * 2 + b_k8) * 16;
                uint32_t r0, r1, r2, r3;
                ldm_x4(r0, r1, r2, r3, addr);
                bf[nb * 2][0] = r0;     bf[nb * 2][1] = r1;
                bf[nb * 2 + 1][0] = r2; bf[nb * 2 + 1][1] = r3;
            }
            #pragma unroll
            for (int mi = 0; mi < 4; mi++)
                #pragma unroll
                for (int nj = 0; nj < 8; nj++)
                    mma16816(acc[mi][nj], af[mi], bf[nj]);
        }
        s = (s == 2) ? 0 : s + 1;
        s2 = (s2 == 2) ? 0 : s2 + 1;
    }

    const int tq = lane >> 2, tr = lane & 3;

    if (!phase2) {
        // ---------- GEMM1 epilogue: +bias, f16 H1, signal f1 ----------
        #pragma unroll
        for (int nj = 0; nj < 8; nj++) {
            const int col = n0 + wn * 64 + nj * 8 + tr * 2;
            const float bx = bias[col], by = bias[col + 1];
            #pragma unroll
            for (int mi = 0; mi < 4; mi++) {
                const int row = m0 + wm * 64 + mi * 16 + tq;
                __half2 h0 = __floats2half2_rn(acc[mi][nj][0] + bx, acc[mi][nj][1] + by);
                __half2 h1v = __floats2half2_rn(acc[mi][nj][2] + bx, acc[mi][nj][3] + by);
                *reinterpret_cast<__half2*>(H1 + (size_t)row * HID + col) = h0;
                *reinterpret_cast<__half2*>(H1 + (size_t)(row + 8) * HID + col) = h1v;
            }
        }
        __threadfence();
        __syncthreads();
        if (tid == 0) atomicAdd(&f1[mt], 1);
        return;
    }

    // ---------- GEMM2 epilogue: relu -> smem tile -> head partials -> HS ----------
    __syncthreads();
    #pragma unroll
    for (int nj = 0; nj < 8; nj++) {
        const int coll = wn * 64 + nj * 8 + tr * 2;
        const float bx = bias[n0 + coll], by = bias[n0 + coll + 1];
        #pragma unroll
        for (int mi = 0; mi < 4; mi++) {
            const int rowl = wm * 64 + mi * 16 + tq;
            __half2 h0 = __floats2half2_rn(fmaxf(acc[mi][nj][0] + bx, 0.f),
                                           fmaxf(acc[mi][nj][1] + by, 0.f));
            __half2 h1v = __floats2half2_rn(fmaxf(acc[mi][nj][2] + bx, 0.f),
                                            fmaxf(acc[mi][nj][3] + by, 0.f));
            *reinterpret_cast<__half2*>(smem + rowl * TILE_PITCH + coll * 2) = h0;
            *reinterpret_cast<__half2*>(smem + (rowl + 8) * TILE_PITCH + coll * 2) = h1v;
        }
    }
    {
        const int col = n0 + tid;
        const float4* Wc4 = reinterpret_cast<const float4*>(WcH);
        const float4* Wr4 = reinterpret_cast<const float4*>(WrH);
        float4* w = reinterpret_cast<float4*>(smem + WSM_OFF + tid * 64);
        w[0] = __ldg(Wc4 + col);
        w[1] = __ldg(Wr4 + 3 * col);
        w[2] = __ldg(Wr4 + 3 * col + 1);
        w[3] = __ldg(Wr4 + 3 * col + 2);
    }
    __syncthreads();
    {
        float po[16];
        #pragma unroll
        for (int o = 0; o < 16; o++) po[o] = 0.f;
        const char* trow = smem + tid * TILE_PITCH;
        #pragma unroll 4
        for (int j = 0; j < 32; j++) {
            uint2 hv = *reinterpret_cast<const uint2*>(trow + j * 8);
            const __half2* hp = reinterpret_cast<const __half2*>(&hv);
            float2 f0 = __half22float2(hp[0]), f1v = __half22float2(hp[1]);
            float hvv[4] = { f0.x, f0.y, f1v.x, f1v.y };
            #pragma unroll
            for (int q = 0; q < 4; q++) {
                const float v = hvv[q];
                const float4* w = reinterpret_cast<const float4*>(smem + WSM_OFF + (4 * j + q) * 64);
                float4 a = w[0], b2v = w[1], c2 = w[2], d = w[3];
                po[0]  += v * a.x;   po[1]  += v * a.y;   po[2]  += v * a.z;   po[3]  += v * a.w;
                po[4]  += v * b2v.x; po[5]  += v * b2v.y; po[6]  += v * b2v.z; po[7]  += v * b2v.w;
                po[8]  += v * c2.x;  po[9]  += v * c2.y;  po[10] += v * c2.z;  po[11] += v * c2.w;
                po[12] += v * d.x;   po[13] += v * d.y;   po[14] += v * d.z;   po[15] += v * d.w;
            }
        }
        float* gs = HS + (size_t)(m0 + tid) * 16;
        #pragma unroll
        for (int o = 0; o < 16; o++) atomicAdd(gs + o, po[o]);
    }
    __threadfence();
    __syncthreads();
    if (tid == 0) sTicket = atomicAdd(&f2[mt], 1);
    __syncthreads();
    if (sTicket != 7) return;

    // ---------- last tile of this m-tile: finalize 128 rows ----------
    {
        const int row = m0 + tid;
        const float4* p = reinterpret_cast<const float4*>(HS + (size_t)row * 16);
        float4 v0 = __ldcg(p), v1 = __ldcg(p + 1), v2 = __ldcg(p + 2), v3 = __ldcg(p + 3);
        float res[16] = { v0.x, v0.y, v0.z, v0.w, v1.x, v1.y, v1.z, v1.w,
                          v2.x, v2.y, v2.z, v2.w, v3.x, v3.y, v3.z, v3.w };
        #pragma unroll
        for (int o = 0; o < 16; o++)
            res[o] += (o < 4) ? __ldg(&bc[o]) : __ldg(&br[o - 4]);
        float m = fmaxf(fmaxf(res[0], res[1]), fmaxf(res[2], res[3]));
        float e0 = expf(res[0] - m), e1 = expf(res[1] - m), e2 = expf(res[2] - m), e3 = expf(res[3] - m);
        float inv = 1.f / (e0 + e1 + e2 + e3);
        out[(size_t)row * 4 + 0] = e0 * inv;
        out[(size_t)row * 4 + 1] = e1 * inv;
        out[(size_t)row * 4 + 2] = e2 * inv;
        out[(size_t)row * 4 + 3] = e3 * inv;
        float* box = out + (size_t)NROWS * 4 + (size_t)row * 12;
        #pragma unroll
        for (int o = 0; o < 12; o++) box[o] = res[o + 4];
    }
}

// ---------------- launch ----------------
extern "C" void kernel_launch(void* const* d_in, const int* in_sizes, int n_in,
                              void* d_out, int out_size) {
    (void)in_sizes; (void)n_in; (void)out_size;
    const float* X  = (const float*)d_in[0];
    const float* W1 = (const float*)d_in[1];
    const float* b1 = (const float*)d_in[2];
    const float* W2 = (const float*)d_in[3];
    const float* b2 = (const float*)d_in[4];
    const float* Wc = (const float*)d_in[5];
    const float* bc = (const float*)d_in[6];
    const float* Wr = (const float*)d_in[7];
    const float* br = (const float*)d_in[8];
    float* out = (float*)d_out;

    void *pXh, *pW1T, *pW2T, *pH1, *pHS, *pFc, *pF1, *pF2;
    cudaGetSymbolAddress(&pXh,  g_Xh);
    cudaGetSymbolAddress(&pW1T, g_W1T);
    cudaGetSymbolAddress(&pW2T, g_W2T);
    cudaGetSymbolAddress(&pH1,  g_H1);
    cudaGetSymbolAddress(&pHS,  g_HS);
    cudaGetSymbolAddress(&pFc,  g_fc);
    cudaGetSymbolAddress(&pF1,  g_f1);
    cudaGetSymbolAddress(&pF2,  g_f2);

    cudaFuncSetAttribute(fused_kernel, cudaFuncAttributeMaxDynamicSharedMemorySize, SMEM_BYTES);

    // 1) prep: X rows [0,3584) -> fp16, W1/W2 transposed f16, zero HS + flags
    prep_kernel<<<PREP_BLOCKS, 256>>>(X, (__half*)pXh, W1, (__half*)pW1T, W2, (__half*)pW2T,
                                      (float*)pHS, (int*)pFc, (int*)pF1, (int*)pF2);
    // 2) fused: converters + GEMM1 + GEMM2(+head partials) + finalize, one launch
    fused_kernel<<<GRID_TOTAL, 128, SMEM_BYTES>>>(
        (const __half*)pXh, (const __half*)pW1T, (const __half*)pW2T,
        b1, b2, (__half*)pH1, (float*)pHS, Wc, Wr, bc, br,
        X, (__half*)pXh, (int*)pFc, (int*)pF1, (int*)pF2, out);
}

// round 16
// speedup vs baseline: 1.0358x; 1.0358x over previous
#include <cuda_runtime.h>
#include <cuda_fp16.h>
#include <cstdint>

// ---------------- problem constants ----------------
#define NROWS 8192
#define DIN   12544
#define HID   1024

// ---------------- GEMM tile config: 128x128 tile, 4 warps (64x64 warp tile) ----------------
#define BM 128
#define BN 128
#define BK 64
#define ROWB 144                           // 128B data + 16B pad (conflict-free ldmatrix)
#define STAGE_BYTES ((BM + BN) * ROWB)     // 36864
#define SMEM_BYTES (3 * STAGE_BYTES)       // 110592 -> 2 CTAs/SM

// fused-epilogue smem layout (within the same dynamic smem, after mainloop)
#define TILE_PITCH 264
#define WSM_OFF    34048

// in-GEMM1 conversion: prep pre-converts m-tiles 0..27 (rows < 3584);
// 72 converter CTAs (2 per m-tile) handle m-tiles 28..63.
#define NCONV      72
#define PRECONV_MT 28
#define WAVE1_G    (PRECONV_MT * 8)        // 224 gemm tiles safe in wave 1

// prep kernel sections
#define CONV_BLOCKS 21952                  // 3584*12544/8/256
#define W1T_BX 32
#define W1T_BLOCKS (W1T_BX * (DIN / 32))   // 12544
#define W2T_BX 32
#define W2T_BLOCKS (W2T_BX * (HID / 32))   // 1024
#define ZERO_BLOCKS 128                    // g_HS: 8192*16 f32
#define PREP_BLOCKS (CONV_BLOCKS + W1T_BLOCKS + W2T_BLOCKS + ZERO_BLOCKS + 1)

// ---------------- device scratch ----------------
__device__ __align__(256) __half g_Xh [(size_t)NROWS * DIN];
__device__ __align__(256) __half g_W1T[(size_t)HID * DIN];
__device__ __align__(256) __half g_W2T[(size_t)HID * HID];
__device__ __align__(256) __half g_H1 [(size_t)NROWS * HID];
__device__ __align__(256) float  g_HS [(size_t)NROWS * 16];   // head partial sums
__device__ __align__(256) int    g_fc[64];                    // converter flags (->2)
__device__ __align__(256) int    g_f2[64];                    // gemm2 finalize tickets (->8)

// ---------------- PTX helpers ----------------
__device__ __forceinline__ uint32_t smem_u32(const void* p) {
    uint32_t a;
    asm("{ .reg .u64 t; cvta.to.shared.u64 t, %1; cvt.u32.u64 %0, t; }" : "=r"(a) : "l"(p));
    return a;
}

#define CP_ASYNC16(dst, src) \
    asm volatile("cp.async.cg.shared.global [%0], [%1], 16;" :: "r"(dst), "l"(src) : "memory")
#define CP_ASYNC_COMMIT() asm volatile("cp.async.commit_group;" ::: "memory")
#define CP_ASYNC_WAIT1()  asm volatile("cp.async.wait_group 1;" ::: "memory")

__device__ __forceinline__ void ldm_x4(uint32_t& r0, uint32_t& r1, uint32_t& r2, uint32_t& r3,
                                       uint32_t addr) {
    asm volatile("ldmatrix.sync.aligned.m8n8.x4.shared.b16 {%0,%1,%2,%3}, [%4];"
                 : "=r"(r0), "=r"(r1), "=r"(r2), "=r"(r3) : "r"(addr));
}

__device__ __forceinline__ void mma16816(float* d, const uint32_t* a, const uint32_t* b) {
    asm volatile(
        "mma.sync.aligned.m16n8k16.row.col.f32.f16.f16.f32 "
        "{%0,%1,%2,%3}, {%4,%5,%6,%7}, {%8,%9}, {%0,%1,%2,%3};"
        : "+f"(d[0]), "+f"(d[1]), "+f"(d[2]), "+f"(d[3])
        : "r"(a[0]), "r"(a[1]), "r"(a[2]), "r"(a[3]), "r"(b[0]), "r"(b[1]));
}

// ---------------- prep: partial X convert + W1/W2 transpose + zero HS/flags ----------------
__global__ void __launch_bounds__(256) prep_kernel(const float* __restrict__ X, __half* __restrict__ Xh,
                                                   const float* __restrict__ W1, __half* __restrict__ W1T,
                                                   const float* __restrict__ W2, __half* __restrict__ W2T,
                                                   float* __restrict__ HS,
                                                   int* __restrict__ fc, int* __restrict__ f2) {
    __shared__ float tile[32][33];
    const int b   = blockIdx.x;
    const int tid = threadIdx.x;

    if (b < CONV_BLOCKS) {
        // X rows [0, 3584) -> fp16
        size_t i = (size_t)b * 256 + tid;
        const float4* p = reinterpret_cast<const float4*>(X) + i * 2;
        float4 a = p[0], c = p[1];
        __half2 h0 = __floats2half2_rn(a.x, a.y), h1 = __floats2half2_rn(a.z, a.w);
        __half2 h2 = __floats2half2_rn(c.x, c.y), h3 = __floats2half2_rn(c.z, c.w);
        uint4 v;
        v.x = *reinterpret_cast<uint32_t*>(&h0);
        v.y = *reinterpret_cast<uint32_t*>(&h1);
        v.z = *reinterpret_cast<uint32_t*>(&h2);
        v.w = *reinterpret_cast<uint32_t*>(&h3);
        reinterpret_cast<uint4*>(Xh)[i] = v;
        return;
    }
    if (b >= CONV_BLOCKS + W1T_BLOCKS + W2T_BLOCKS) {
        const int zb = b - (CONV_BLOCKS + W1T_BLOCKS + W2T_BLOCKS);
        if (zb < ZERO_BLOCKS) {
            size_t i = (size_t)zb * 256 + tid;
            reinterpret_cast<uint4*>(HS)[i] = make_uint4(0, 0, 0, 0);
        } else if (tid < 64) {
            fc[tid] = 0; f2[tid] = 0;
        }
        return;
    }

    const float* in; __half* out; int R, C, idx, bx;
    if (b < CONV_BLOCKS + W1T_BLOCKS) {
        idx = b - CONV_BLOCKS; in = W1; out = W1T; R = DIN; C = HID; bx = W1T_BX;
    } else {
        idx = b - CONV_BLOCKS - W1T_BLOCKS; in = W2; out = W2T; R = HID; C = HID; bx = W2T_BX;
    }
    const int c0 = (idx % bx) * 32, r0 = (idx / bx) * 32;
    const int x = tid & 31, y = tid >> 5;
    #pragma unroll
    for (int j = 0; j < 32; j += 8)
        tile[y + j][x] = in[(size_t)(r0 + y + j) * C + (c0 + x)];
    __syncthreads();
    #pragma unroll
    for (int j = 0; j < 32; j += 8)
        out[(size_t)(c0 + y + j) * R + (r0 + x)] = __float2half_rn(tile[x][y + j]);
}

// ---------------- mma.sync GEMM: 128 threads / 4 warps, warp tile 64x64, 2 CTAs/SM ----------------
// MODE 0 (GEMM1): 1-D grid 584; bids 0..71 convert X m-tiles 28..63 (2 CTAs each);
//                 bids 72.. are tiles g=bid-72 (m=g>>3, n=g&7); g>=224 waits on flag.
//                 Epilogue: +bias, f16 store to H1.
// MODE 1 (GEMM2): 2-D grid; epilogue relu(+bias) -> smem -> head partials -> atomicAdd g_HS;
//                 last n-tile per m-tile (ticket) finalizes softmax + boxes.
template<int MODE>
__global__ void __launch_bounds__(128, 2)
gemm_f16_kernel(const __half* __restrict__ A, const __half* __restrict__ B,
                const float* __restrict__ bias, void* __restrict__ Cout,
                const float* __restrict__ WcH, const float* __restrict__ WrH,
                const float* __restrict__ bc, const float* __restrict__ br,
                float* __restrict__ out,
                const float* __restrict__ Xf, __half* __restrict__ XhW,
                int* __restrict__ fc, int* __restrict__ f2,
                int K, int nk) {
    extern __shared__ char smem[];
    __shared__ int sTicket;
    const uint32_t sb = smem_u32(smem);
    const int tid  = threadIdx.x;
    const int wid  = tid >> 5, lane = tid & 31;
    const int wm   = wid & 1;
    const int wn   = wid >> 1;

    int m0, n0, mt;
    if (MODE == 0) {
        if (blockIdx.x < NCONV) {
            // ---- converter CTA: 64 rows of X starting at row 3584 + cid*64 ----
            const int cid = blockIdx.x;
            const int cmt = PRECONV_MT + (cid >> 1);
            const size_t elem0 = ((size_t)cmt * 128 + (size_t)(cid & 1) * 64) * DIN;
            const float4* src = reinterpret_cast<const float4*>(Xf + elem0);
            uint2* dst = reinterpret_cast<uint2*>(XhW + elem0);
            const int total = 64 * DIN / 4;
            for (int j = tid; j < total; j += 128) {
                float4 v = __ldg(src + j);
                __half2 h0 = __floats2half2_rn(v.x, v.y), h1 = __floats2half2_rn(v.z, v.w);
                uint2 o;
                o.x = *reinterpret_cast<uint32_t*>(&h0);
                o.y = *reinterpret_cast<uint32_t*>(&h1);
                dst[j] = o;
            }
            __threadfence();
            __syncthreads();
            if (tid == 0) atomicAdd(&fc[cmt], 1);
            return;
        }
        const int g = blockIdx.x - NCONV;
        mt = g >> 3;
        m0 = mt * BM;
        n0 = (g & 7) * BN;
        if (g >= WAVE1_G) {
            if (tid == 0) {
                while (atomicAdd(&fc[mt], 0) < 2) __nanosleep(200);
            }
            __syncthreads();
        }
    } else {
        mt = blockIdx.y;
        m0 = mt * BM;
        n0 = blockIdx.x * BN;
    }

    const int cr = tid >> 3;
    const int cc = (tid & 7) * 16;

    const char* gA = reinterpret_cast<const char*>(A) + ((size_t)(m0 + cr) * K) * 2 + cc;
    const char* gB = reinterpret_cast<const char*>(B) + ((size_t)(n0 + cr) * K) * 2 + cc;
    const size_t rstride = (size_t)16 * K * 2;

    auto issue_stage = [&](int kc, int s) {
        const uint32_t abase = sb + s * STAGE_BYTES;
        const uint32_t bbase = abase + BM * ROWB;
        const size_t koff = (size_t)kc * (BK * 2);
        #pragma unroll
        for (int h = 0; h < 8; h++)
            CP_ASYNC16(abase + (cr + h * 16) * ROWB + cc, gA + koff + h * rstride);
        #pragma unroll
        for (int h = 0; h < 8; h++)
            CP_ASYNC16(bbase + (cr + h * 16) * ROWB + cc, gB + koff + h * rstride);
    };

    const int a_row = lane & 15, a_k8 = lane >> 4;
    const int b_row = (lane & 7) + ((lane >> 4) << 3), b_k8 = (lane >> 3) & 1;

    float acc[4][8][4];
    #pragma unroll
    for (int i = 0; i < 4; i++)
        #pragma unroll
        for (int j = 0; j < 8; j++)
            #pragma unroll
            for (int r = 0; r < 4; r++) acc[i][j][r] = 0.f;

    issue_stage(0, 0); CP_ASYNC_COMMIT();
    if (nk > 1) issue_stage(1, 1); CP_ASYNC_COMMIT();

    int s = 0, s2 = 2;
    for (int kc = 0; kc < nk; kc++) {
        CP_ASYNC_WAIT1();
        __syncthreads();

        if (kc + 2 < nk) issue_stage(kc + 2, s2);
        CP_ASYNC_COMMIT();

        const uint32_t abase = sb + s * STAGE_BYTES;
        const uint32_t bbase = abase + BM * ROWB;

        #pragma unroll
        for (int kk = 0; kk < 4; kk++) {
            uint32_t af[4][4], bf[8][2];
            #pragma unroll
            for (int mi = 0; mi < 4; mi++) {
                uint32_t addr = abase + (wm * 64 + mi * 16 + a_row) * ROWB + (kk * 2 + a_k8) * 16;
                ldm_x4(af[mi][0], af[mi][1], af[mi][2], af[mi][3], addr);
            }
            #pragma unroll
            for (int nb = 0; nb < 4; nb++) {
                uint32_t addr = bbase + (wn * 64 + nb * 16 + b_row) * ROWB + (kk * 2 + b_k8) * 16;
                uint32_t r0, r1, r2, r3;
                ldm_x4(r0, r1, r2, r3, addr);
                bf[nb * 2][0] = r0;     bf[nb * 2][1] = r1;
                bf[nb * 2 + 1][0] = r2; bf[nb * 2 + 1][1] = r3;
            }
            #pragma unroll
            for (int mi = 0; mi < 4; mi++)
                #pragma unroll
                for (int nj = 0; nj < 8; nj++)
                    mma16816(acc[mi][nj], af[mi], bf[nj]);
        }
        s = (s == 2) ? 0 : s + 1;
        s2 = (s2 == 2) ? 0 : s2 + 1;
    }

    const int tq = lane >> 2, tr = lane & 3;

    if (MODE == 0) {
        __half* C = reinterpret_cast<__half*>(Cout);
        #pragma unroll
        for (int nj = 0; nj < 8; nj++) {
            const int col = n0 + wn * 64 + nj * 8 + tr * 2;
            const float bx = bias[col], by = bias[col + 1];
            #pragma unroll
            for (int mi = 0; mi < 4; mi++) {
                const int row = m0 + wm * 64 + mi * 16 + tq;
                __half2 h0 = __floats2half2_rn(acc[mi][nj][0] + bx, acc[mi][nj][1] + by);
                __half2 h1 = __floats2half2_rn(acc[mi][nj][2] + bx, acc[mi][nj][3] + by);
                *reinterpret_cast<__half2*>(C + (size_t)row * HID + col) = h0;
                *reinterpret_cast<__half2*>(C + (size_t)(row + 8) * HID + col) = h1;
            }
        }
        return;
    }

    // ================= MODE 1: fused relu + head partials + ticket finalize =================
    __syncthreads();

    #pragma unroll
    for (int nj = 0; nj < 8; nj++) {
        const int coll = wn * 64 + nj * 8 + tr * 2;
        const float bx = bias[n0 + coll], by = bias[n0 + coll + 1];
        #pragma unroll
        for (int mi = 0; mi < 4; mi++) {
            const int rowl = wm * 64 + mi * 16 + tq;
            __half2 h0 = __floats2half2_rn(fmaxf(acc[mi][nj][0] + bx, 0.f),
                                           fmaxf(acc[mi][nj][1] + by, 0.f));
            __half2 h1 = __floats2half2_rn(fmaxf(acc[mi][nj][2] + bx, 0.f),
                                           fmaxf(acc[mi][nj][3] + by, 0.f));
            *reinterpret_cast<__half2*>(smem + rowl * TILE_PITCH + coll * 2) = h0;
            *reinterpret_cast<__half2*>(smem + (rowl + 8) * TILE_PITCH + coll * 2) = h1;
        }
    }

    {
        const int col = n0 + tid;
        const float4* Wc4 = reinterpret_cast<const float4*>(WcH);
        const float4* Wr4 = reinterpret_cast<const float4*>(WrH);
        float4* w = reinterpret_cast<float4*>(smem + WSM_OFF + tid * 64);
        w[0] = __ldg(Wc4 + col);
        w[1] = __ldg(Wr4 + 3 * col);
        w[2] = __ldg(Wr4 + 3 * col + 1);
        w[3] = __ldg(Wr4 + 3 * col + 2);
    }
    __syncthreads();

    {
        float po[16];
        #pragma unroll
        for (int o = 0; o < 16; o++) po[o] = 0.f;
        const char* trow = smem + tid * TILE_PITCH;
        #pragma unroll 4
        for (int j = 0; j < 32; j++) {
            uint2 hv = *reinterpret_cast<const uint2*>(trow + j * 8);
            const __half2* hp = reinterpret_cast<const __half2*>(&hv);
            float2 f0 = __half22float2(hp[0]), f1 = __half22float2(hp[1]);
            float hvv[4] = { f0.x, f0.y, f1.x, f1.y };
            #pragma unroll
            for (int q = 0; q < 4; q++) {
                const float v = hvv[q];
                const float4* w = reinterpret_cast<const float4*>(smem + WSM_OFF + (4 * j + q) * 64);
                float4 a = w[0], b2 = w[1], c2 = w[2], d = w[3];
                po[0]  += v * a.x;  po[1]  += v * a.y;  po[2]  += v * a.z;  po[3]  += v * a.w;
                po[4]  += v * b2.x; po[5]  += v * b2.y; po[6]  += v * b2.z; po[7]  += v * b2.w;
                po[8]  += v * c2.x; po[9]  += v * c2.y; po[10] += v * c2.z; po[11] += v * c2.w;
                po[12] += v * d.x;  po[13] += v * d.y;  po[14] += v * d.z;  po[15] += v * d.w;
            }
        }
        float* gs = reinterpret_cast<float*>(Cout) + (size_t)(m0 + tid) * 16;
        #pragma unroll
        for (int o = 0; o < 16; o++) atomicAdd(gs + o, po[o]);
    }

    __threadfence();
    __syncthreads();
    if (tid == 0) sTicket = atomicAdd(&f2[mt], 1);
    __syncthreads();
    if (sTicket != 7) return;

    // ---- last n-tile of this m-tile: finalize 128 rows ----
    {
        const int row = m0 + tid;
        const float4* p = reinterpret_cast<const float4*>(
            reinterpret_cast<const float*>(Cout) + (size_t)row * 16);
        float4 v0 = __ldcg(p), v1 = __ldcg(p + 1), v2 = __ldcg(p + 2), v3 = __ldcg(p + 3);
        float res[16] = { v0.x, v0.y, v0.z, v0.w, v1.x, v1.y, v1.z, v1.w,
                          v2.x, v2.y, v2.z, v2.w, v3.x, v3.y, v3.z, v3.w };
        #pragma unroll
        for (int o = 0; o < 16; o++)
            res[o] += (o < 4) ? __ldg(&bc[o]) : __ldg(&br[o - 4]);
        float m = fmaxf(fmaxf(res[0], res[1]), fmaxf(res[2], res[3]));
        float e0 = expf(res[0] - m), e1 = expf(res[1] - m), e2 = expf(res[2] - m), e3 = expf(res[3] - m);
        float inv = 1.f / (e0 + e1 + e2 + e3);
        out[(size_t)row * 4 + 0] = e0 * inv;
        out[(size_t)row * 4 + 1] = e1 * inv;
        out[(size_t)row * 4 + 2] = e2 * inv;
        out[(size_t)row * 4 + 3] = e3 * inv;
        float* box = out + (size_t)NROWS * 4 + (size_t)row * 12;
        #pragma unroll
        for (int o = 0; o < 12; o++) box[o] = res[o + 4];
    }
}

// ---------------- launch (single stream, serial) ----------------
extern "C" void kernel_launch(void* const* d_in, const int* in_sizes, int n_in,
                              void* d_out, int out_size) {
    (void)in_sizes; (void)n_in; (void)out_size;
    const float* X  = (const float*)d_in[0];
    const float* W1 = (const float*)d_in[1];
    const float* b1 = (const float*)d_in[2];
    const float* W2 = (const float*)d_in[3];
    const float* b2 = (const float*)d_in[4];
    const float* Wc = (const float*)d_in[5];
    const float* bc = (const float*)d_in[6];
    const float* Wr = (const float*)d_in[7];
    const float* br = (const float*)d_in[8];
    float* out = (float*)d_out;

    void *pXh, *pW1T, *pW2T, *pH1, *pHS, *pFc, *pF2;
    cudaGetSymbolAddress(&pXh,  g_Xh);
    cudaGetSymbolAddress(&pW1T, g_W1T);
    cudaGetSymbolAddress(&pW2T, g_W2T);
    cudaGetSymbolAddress(&pH1,  g_H1);
    cudaGetSymbolAddress(&pHS,  g_HS);
    cudaGetSymbolAddress(&pFc,  g_fc);
    cudaGetSymbolAddress(&pF2,  g_f2);

    cudaFuncSetAttribute(gemm_f16_kernel<0>, cudaFuncAttributeMaxDynamicSharedMemorySize, SMEM_BYTES);
    cudaFuncSetAttribute(gemm_f16_kernel<1>, cudaFuncAttributeMaxDynamicSharedMemorySize, SMEM_BYTES);

    // 1) prep: X rows [0,3584) -> fp16, W1/W2 transposed f16, zero HS + flags
    prep_kernel<<<PREP_BLOCKS, 256>>>(X, (__half*)pXh, W1, (__half*)pW1T, W2, (__half*)pW2T,
                                      (float*)pHS, (int*)pFc, (int*)pF2);
    // 2) GEMM1 (1-D grid: 72 converters + 512 tiles): H1 = X @ W1 + b1
    gemm_f16_kernel<0><<<NCONV + 512, 128, SMEM_BYTES>>>(
        (const __half*)pXh, (const __half*)pW1T, b1, pH1,
        nullptr, nullptr, nullptr, nullptr, nullptr,
        X, (__half*)pXh, (int*)pFc, nullptr, DIN, DIN / BK);
    // 3) fused GEMM2: relu(H1 @ W2 + b2) -> head partials -> ticket finalize (softmax+boxes)
    gemm_f16_kernel<1><<<dim3(HID / BN, NROWS / BM), 128, SMEM_BYTES>>>(
        (const __half*)pH1, (const __half*)pW2T, b2, pHS,
        Wc, Wr, bc, br, out,
        nullptr, nullptr, nullptr, (int*)pF2, HID, HID / BK);
}